// round 10
// baseline (speedup 1.0000x reference)
#include <cuda_runtime.h>

#define NN 50000
#define NE 800000
#define DIN 7
#define DD 64
#define GG 64
#define NB_SCAN 196   // ceil(NN/256)
#define NT 64         // nodes per k_layer block
#define NT2 32        // nodes per k_node2 block
#define PAD 36        // k_node2 act row stride
#define PAD2 68       // k_layer act row stride (272B, 16B aligned)

// ---------------- scratch (device globals; no allocation allowed) -------------
__device__ float g_xembA[NN * DD];
__device__ float g_xembB[NN * DD];
__device__ float g_xaggemb[NN * DD];
__device__ float g_degmax[GG];
__device__ float g_gagg[GG * DD];
__device__ float g_gcnt[GG];
__device__ float g_gout[GG * DD];
__device__ int2  g_cw[NE];          // sorted-by-row packed {col, w_bits}
__device__ int   g_rowptr[NN + 1];
__device__ int   g_cnt[NN];         // histogram
__device__ int   g_cnt2[NN];        // scatter cursors
__device__ int   g_bsum[NB_SCAN];
__device__ int   g_boff[NB_SCAN];
__device__ int   g_batch[NN];
__device__ int   g_flag[2];         // 1 => input is int64, 0 => int32

// ---------------- packed f32x2 helpers (sm_100+) -------------------------------
__device__ __forceinline__ unsigned long long pack2(float w) {
    unsigned long long r;
    asm("mov.b64 %0, {%1, %1};" : "=l"(r) : "f"(w));
    return r;
}
__device__ __forceinline__ void ffma2(unsigned long long& d,
                                      unsigned long long a, unsigned long long b) {
    asm("fma.rn.f32x2 %0, %1, %2, %0;" : "+l"(d) : "l"(a), "l"(b));
}
__device__ __forceinline__ void lds_pair(unsigned long long& a, unsigned long long& b,
                                         const float* p) {
    unsigned addr = (unsigned)__cvta_generic_to_shared(p);
    asm("ld.shared.v2.b64 {%0, %1}, [%2];" : "=l"(a), "=l"(b) : "r"(addr));
}
__device__ __forceinline__ float2 unpack2(unsigned long long v) {
    float2 f;
    asm("mov.b64 {%0, %1}, %2;" : "=f"(f.x), "=f"(f.y) : "l"(v));
    return f;
}

// ---------------- vector reduction helper (sm_90+) ----------------------------
__device__ __forceinline__ void red4(float* p, float4 v) {
    asm volatile("red.global.add.v4.f32 [%0], {%1,%2,%3,%4};"
                 :: "l"(p), "f"(v.x), "f"(v.y), "f"(v.z), "f"(v.w)
                 : "memory");
}

// ---------------- fused zero + dtype detection --------------------------------
// All blocks zero scratch; block 0's first two warps detect int64 vs int32 by
// sampling odd 32-bit words (int64 high halves are all zero for graph indices).
__global__ void k_init(const int* __restrict__ eidx, const int* __restrict__ batch) {
    int i = blockIdx.x * blockDim.x + threadIdx.x;
    int4 zi = make_int4(0, 0, 0, 0);
    float4 zf = make_float4(0.f, 0.f, 0.f, 0.f);
    if (i < NN / 4) { ((int4*)g_cnt)[i] = zi; ((int4*)g_cnt2)[i] = zi; }
    if (i < GG * 16) ((float4*)g_gagg)[i] = zf;
    if (i < GG / 4) { ((float4*)g_degmax)[i] = zf; ((float4*)g_gcnt)[i] = zf; }
    if (blockIdx.x == 0 && threadIdx.x < 64) {
        int slot = threadIdx.x >> 5;
        const int* p = slot ? batch : eidx;
        int n32 = slot ? NN : 2 * NE;
        int t = threadIdx.x & 31;
        long long half = (long long)(n32 - 1) / 2;
        long long k = (half > 32) ? ((long long)t * (half - 1)) / 31 : (long long)t;
        long long idx = 2 * k + 1;
        int v = (idx < n32) ? p[idx] : 0;
        unsigned m = __ballot_sync(0xffffffffu, v == 0);
        if (t == 0) g_flag[slot] = (m == 0xffffffffu) ? 1 : 0;
    }
}

// ---------------- row histogram (reads only the row half) ----------------------
__global__ void k_conv_edges(const void* __restrict__ p) {
    int e = blockIdx.x * blockDim.x + threadIdx.x;
    if (e >= NE) return;
    int r;
    if (g_flag[0]) r = (int)((const long long*)p)[NE + e];
    else           r = ((const int*)p)[NE + e];
    atomicAdd(&g_cnt[r], 1);
}

// batch conversion + per-graph degree max + per-graph node count (fused)
__global__ void k_conv_batch(const void* __restrict__ p, const float* __restrict__ degree) {
    int n = blockIdx.x * blockDim.x + threadIdx.x;
    if (n >= NN) return;
    int b;
    if (g_flag[1]) b = (int)((const long long*)p)[n];
    else           b = ((const int*)p)[n];
    g_batch[n] = b;
    atomicMax((unsigned int*)&g_degmax[b], __float_as_uint(degree[n]));
    atomicAdd(&g_gcnt[b], 1.f);
}

// ---------------- 3-kernel exclusive scan of g_cnt -> g_rowptr -----------------
__global__ void k_scanA() {                         // 196 blocks x 256
    __shared__ int sh[256];
    int i = blockIdx.x * 256 + threadIdx.x;
    sh[threadIdx.x] = (i < NN) ? g_cnt[i] : 0;
    __syncthreads();
    for (int s = 128; s > 0; s >>= 1) {
        if (threadIdx.x < s) sh[threadIdx.x] += sh[threadIdx.x + s];
        __syncthreads();
    }
    if (threadIdx.x == 0) g_bsum[blockIdx.x] = sh[0];
}

__global__ void k_scanB() {                         // 1 block x 256
    __shared__ int sh[256];
    int t = threadIdx.x;
    int v = (t < NB_SCAN) ? g_bsum[t] : 0;
    sh[t] = v;
    __syncthreads();
    for (int s = 1; s < 256; s <<= 1) {
        int add = (t >= s) ? sh[t - s] : 0;
        __syncthreads();
        sh[t] += add;
        __syncthreads();
    }
    if (t < NB_SCAN) g_boff[t] = sh[t] - v;         // exclusive
    if (t == 0) g_rowptr[NN] = NE;
}

__global__ void k_scanC() {                         // 196 blocks x 256
    __shared__ int sh[256];
    int t = threadIdx.x;
    int i = blockIdx.x * 256 + t;
    int v = (i < NN) ? g_cnt[i] : 0;
    sh[t] = v;
    __syncthreads();
    for (int s = 1; s < 256; s <<= 1) {
        int add = (t >= s) ? sh[t - s] : 0;
        __syncthreads();
        sh[t] += add;
        __syncthreads();
    }
    if (i < NN) g_rowptr[i] = g_boff[blockIdx.x] + sh[t] - v;
}

// scatter edges into CSR order, packing {col, w}; reads raw edge input again
__global__ void k_scatter(const void* __restrict__ p, const float* __restrict__ ea) {
    int e = blockIdx.x * blockDim.x + threadIdx.x;
    if (e >= NE) return;
    int c, r;
    if (g_flag[0]) {
        const long long* q = (const long long*)p;
        c = (int)q[e]; r = (int)q[NE + e];
    } else {
        const int* q = (const int*)p;
        c = q[e]; r = q[NE + e];
    }
    int pos = g_rowptr[r] + atomicAdd(&g_cnt2[r], 1);
    g_cw[pos] = make_int2(c, __float_as_int(ea[e]));
}

// ---------------- node embedding: x_emb = relu(x @ W_en + b_en) ---------------
__global__ void k_nodeemb(const float* __restrict__ x,
                          const float* __restrict__ W,
                          const float* __restrict__ b) {
    __shared__ float sx[4][DIN];
    int gl = threadIdx.x >> 6, o = threadIdx.x & 63;
    int n = blockIdx.x * 4 + gl;
    if (o < DIN && n < NN) sx[gl][o] = x[n * DIN + o];
    __syncthreads();
    if (n >= NN) return;
    float acc = b[o];
#pragma unroll
    for (int i = 0; i < DIN; i++) acc = fmaf(sx[gl][i], W[i * DD + o], acc);
    g_xembA[n * DD + o] = fmaxf(acc, 0.f);
}

// ---------------- fused stage-2: 32 nodes/block -------------------------------
__global__ void __launch_bounds__(256) k_node2(
        const float* __restrict__ x,
        const float* __restrict__ Wene, const float* __restrict__ bene,
        const float* __restrict__ Wagg, const float* __restrict__ bagg) {
    __shared__ __align__(16) float act[DD][PAD];
    __shared__ float ne[NT2][9];
    __shared__ float rcs[NT2];
    int t = threadIdx.x;
    int n0 = blockIdx.x * NT2;

    // ---- gather (unroll 4 for MLP) ----
    {
        int ln = t >> 3, f = t & 7;
        int n = n0 + ln;
        float acc = 0.f;
        int deg = 0;
        if (n < NN) {
            int p0 = g_rowptr[n];
            deg = g_rowptr[n + 1] - p0;
            int k = 0;
            for (; k + 4 <= deg; k += 4) {
                int2 c0 = g_cw[p0 + k],     c1 = g_cw[p0 + k + 1];
                int2 c2 = g_cw[p0 + k + 2], c3 = g_cw[p0 + k + 3];
                float v0 = (f < 7) ? x[c0.x * DIN + f] : __int_as_float(c0.y);
                float v1 = (f < 7) ? x[c1.x * DIN + f] : __int_as_float(c1.y);
                float v2 = (f < 7) ? x[c2.x * DIN + f] : __int_as_float(c2.y);
                float v3 = (f < 7) ? x[c3.x * DIN + f] : __int_as_float(c3.y);
                acc += (v0 + v1) + (v2 + v3);
            }
            for (; k < deg; k++) {
                int2 cw = g_cw[p0 + k];
                acc += (f < 7) ? x[cw.x * DIN + f] : __int_as_float(cw.y);
            }
        }
        ne[ln][f] = acc;
        if (f == 0) rcs[ln] = 1.f / fmaxf((float)deg, 1.f);
    }
    __syncthreads();

    // ---- ene GEMM + degree slot -> act[o][node] ----
    {
        int gl = t >> 6, o = t & 63;
        float wv[8], b0 = 0.f;
        if (o < 63) {
            b0 = bene[o];
#pragma unroll
            for (int j = 0; j < 8; j++) wv[j] = Wene[j * 63 + o];
        }
#pragma unroll
        for (int i = 0; i < 8; i++) {
            int node = gl * 8 + i;
            int n = n0 + node;
            float v;
            if (o < 63) {
                float rc = rcs[node];
                float a = b0;
#pragma unroll
                for (int j = 0; j < 8; j++) a = fmaf(ne[node][j] * rc, wv[j], a);
                v = fmaxf(a, 0.f);
            } else {
                v = (n < NN) ? g_degmax[g_batch[n]] : 0.f;
            }
            act[o][node] = v;
        }
    }
    __syncthreads();

    // ---- Wagg GEMM (FFMA2): x_agg_emb = relu(act @ Wagg + bagg) ----
    {
        int gl = t >> 6, o = t & 63;
        unsigned long long m01, m23, m45, m67;
        m01 = m23 = m45 = m67 = pack2(bagg[o]);
#pragma unroll 4
        for (int j = 0; j < DD; j++) {
            unsigned long long ww = pack2(Wagg[j * DD + o]);
            unsigned long long a0, a1, a2, a3;
            lds_pair(a0, a1, &act[j][gl * 8]);
            lds_pair(a2, a3, &act[j][gl * 8 + 4]);
            ffma2(m01, ww, a0); ffma2(m23, ww, a1);
            ffma2(m45, ww, a2); ffma2(m67, ww, a3);
        }
        float2 r0 = unpack2(m01), r1 = unpack2(m23);
        float2 r2 = unpack2(m45), r3 = unpack2(m67);
        float res[8] = {r0.x, r0.y, r1.x, r1.y, r2.x, r2.y, r3.x, r3.y};
#pragma unroll
        for (int i = 0; i < 8; i++) {
            int n = n0 + gl * 8 + i;
            if (n < NN) g_xaggemb[n * DD + o] = fmaxf(res[i], 0.f);
        }
    }
}

// ---------------- fused per-layer: float2 gather + FFMA2 GEMMs, NT=64 ---------
// Dynamic smem: act1[128][PAD2] + act2[128][PAD2] = 69,632 bytes.
// Gather: warp-per-node (lane = feature pair), 8 reps x 8 warps.
// GEMM: thread (o = t&63, gl = t>>6) computes column o for 16 nodes via
//       8 f32x2 accumulators; per j: 1 weight LDG + 4 broadcast LDS + 8 FFMA2.
extern __shared__ float s_dyn[];
__global__ void __launch_bounds__(256, 3) k_layer(
        const float* __restrict__ Wm, const float* __restrict__ bm,
        const float* __restrict__ Wu, const float* __restrict__ bu,
        int flip) {
    const float* __restrict__ src = flip ? g_xembB : g_xembA;
    float*       __restrict__ dst = flip ? g_xembA : g_xembB;
    float (*act1)[PAD2] = (float(*)[PAD2])s_dyn;
    float (*act2)[PAD2] = (float(*)[PAD2])(s_dyn + 2 * DD * PAD2);
    int t = threadIdx.x;
    int n0 = blockIdx.x * NT;

    // ---- gather phase ----
    {
        int o2 = t & 31;          // feature pair: features 2*o2, 2*o2+1
        int w8 = t >> 5;          // warp id 0..7
#pragma unroll 1
        for (int rep = 0; rep < 8; rep++) {
            int ln = rep * 8 + w8;
            int n = n0 + ln;
            unsigned long long acc = 0ULL, xe = 0ULL, xae = 0ULL;
            int deg = 0;
            if (n < NN) {
                int p0 = g_rowptr[n];
                deg = g_rowptr[n + 1] - p0;
                int k = 0;
                for (; k + 4 <= deg; k += 4) {
                    int2 c0 = g_cw[p0 + k],     c1 = g_cw[p0 + k + 1];
                    int2 c2 = g_cw[p0 + k + 2], c3 = g_cw[p0 + k + 3];
                    unsigned long long v0 = *(const unsigned long long*)&src[c0.x * DD + 2 * o2];
                    unsigned long long v1 = *(const unsigned long long*)&src[c1.x * DD + 2 * o2];
                    unsigned long long v2 = *(const unsigned long long*)&src[c2.x * DD + 2 * o2];
                    unsigned long long v3 = *(const unsigned long long*)&src[c3.x * DD + 2 * o2];
                    ffma2(acc, pack2(__int_as_float(c0.y)), v0);
                    ffma2(acc, pack2(__int_as_float(c1.y)), v1);
                    ffma2(acc, pack2(__int_as_float(c2.y)), v2);
                    ffma2(acc, pack2(__int_as_float(c3.y)), v3);
                }
                for (; k < deg; k++) {
                    int2 cw = g_cw[p0 + k];
                    unsigned long long v = *(const unsigned long long*)&src[cw.x * DD + 2 * o2];
                    ffma2(acc, pack2(__int_as_float(cw.y)), v);
                }
                xe  = *(const unsigned long long*)&src[n * DD + 2 * o2];
                xae = *(const unsigned long long*)&g_xaggemb[n * DD + 2 * o2];
            }
            float rc = 1.f / fmaxf((float)deg, 1.f);
            float2 a = unpack2(acc), x2 = unpack2(xe), xa2 = unpack2(xae);
            act1[2 * o2][ln]          = a.x * rc;
            act1[2 * o2 + 1][ln]      = a.y * rc;
            act1[DD + 2 * o2][ln]     = xa2.x;
            act1[DD + 2 * o2 + 1][ln] = xa2.y;
            act2[2 * o2][ln]          = x2.x;
            act2[2 * o2 + 1][ln]      = x2.y;
        }
    }
    __syncthreads();

    int gl = t >> 6, o = t & 63;

    // ---- GEMM1: m = relu([xagg, xaggemb] @ Wm + bm) ----
    {
        unsigned long long m[8];
        unsigned long long b0 = pack2(bm[o]);
#pragma unroll
        for (int i = 0; i < 8; i++) m[i] = b0;
#pragma unroll 4
        for (int j = 0; j < 2 * DD; j++) {
            unsigned long long ww = pack2(Wm[j * DD + o]);
            unsigned long long a0, a1, a2, a3, a4, a5, a6, a7;
            lds_pair(a0, a1, &act1[j][gl * 16]);
            lds_pair(a2, a3, &act1[j][gl * 16 + 4]);
            lds_pair(a4, a5, &act1[j][gl * 16 + 8]);
            lds_pair(a6, a7, &act1[j][gl * 16 + 12]);
            ffma2(m[0], ww, a0); ffma2(m[1], ww, a1);
            ffma2(m[2], ww, a2); ffma2(m[3], ww, a3);
            ffma2(m[4], ww, a4); ffma2(m[5], ww, a5);
            ffma2(m[6], ww, a6); ffma2(m[7], ww, a7);
        }
        float* row = &act2[DD + o][gl * 16];
#pragma unroll
        for (int i = 0; i < 8; i++) {
            float2 r = unpack2(m[i]);
            row[2 * i]     = fmaxf(r.x, 0.f);
            row[2 * i + 1] = fmaxf(r.y, 0.f);
        }
    }
    __syncthreads();

    // ---- GEMM2: x_emb' = relu([x_emb, m] @ Wu + bu) ----
    {
        unsigned long long m[8];
        unsigned long long b0 = pack2(bu[o]);
#pragma unroll
        for (int i = 0; i < 8; i++) m[i] = b0;
#pragma unroll 4
        for (int j = 0; j < 2 * DD; j++) {
            unsigned long long ww = pack2(Wu[j * DD + o]);
            unsigned long long a0, a1, a2, a3, a4, a5, a6, a7;
            lds_pair(a0, a1, &act2[j][gl * 16]);
            lds_pair(a2, a3, &act2[j][gl * 16 + 4]);
            lds_pair(a4, a5, &act2[j][gl * 16 + 8]);
            lds_pair(a6, a7, &act2[j][gl * 16 + 12]);
            ffma2(m[0], ww, a0); ffma2(m[1], ww, a1);
            ffma2(m[2], ww, a2); ffma2(m[3], ww, a3);
            ffma2(m[4], ww, a4); ffma2(m[5], ww, a5);
            ffma2(m[6], ww, a6); ffma2(m[7], ww, a7);
        }
#pragma unroll
        for (int i = 0; i < 8; i++) {
            float2 r = unpack2(m[i]);
            int n = n0 + gl * 16 + 2 * i;
            if (n < NN)     dst[n * DD + o]        = fmaxf(r.x, 0.f);
            if (n + 1 < NN) dst[(n + 1) * DD + o]  = fmaxf(r.y, 0.f);
        }
    }
}

// ---------------- graph pooling: sorted-batch local accumulation --------------
__global__ void k_gscatter() {
    int idx = blockIdx.x * blockDim.x + threadIdx.x;   // 50000 threads
    int c  = idx & 15;
    int n0 = (idx >> 4) * 16;
    if (n0 >= NN) return;
    float4 acc = make_float4(0.f, 0.f, 0.f, 0.f);
    int curb = g_batch[n0];
#pragma unroll
    for (int k = 0; k < 16; k++) {
        int n = n0 + k;
        int b = g_batch[n];
        if (b != curb) {
            red4(g_gagg + curb * DD + c * 4, acc);
            acc = make_float4(0.f, 0.f, 0.f, 0.f);
            curb = b;
        }
        float4 v = ((const float4*)g_xembB)[n * 16 + c];
        acc.x += v.x; acc.y += v.y; acc.z += v.z; acc.w += v.w;
    }
    red4(g_gagg + curb * DD + c * 4, acc);
}

__global__ void k_ggemm(const float* __restrict__ Wg, const float* __restrict__ bg) {
    int idx = blockIdx.x * blockDim.x + threadIdx.x;
    if (idx >= GG * DD) return;
    int g = idx >> 6, o = idx & 63;
    float rc = 1.f / fmaxf(g_gcnt[g], 1.f);
    float acc = bg[o];
#pragma unroll 16
    for (int k = 0; k < DD; k++)
        acc = fmaf(g_gagg[g * DD + k] * rc, Wg[k * DD + o], acc);
    g_gout[idx] = acc;   // no relu (reference applies relu to the concat input)
}

// ---------------- readout: q = relu([gout[batch], x_emb]) @ W_r + b_r ----------
__global__ void k_final(const float* __restrict__ Wr, const float* __restrict__ br,
                        float* __restrict__ out) {
    int gidx = blockIdx.x * blockDim.x + threadIdx.x;
    int n = gidx >> 5;
    int lane = threadIdx.x & 31;
    if (n >= NN) return;
    int b = g_batch[n];
    float acc = fmaxf(g_gout[b * DD + lane], 0.f)       * Wr[lane]
              + fmaxf(g_gout[b * DD + 32 + lane], 0.f)  * Wr[32 + lane]
              + g_xembB[n * DD + lane]                   * Wr[DD + lane]      // x_emb >= 0
              + g_xembB[n * DD + 32 + lane]              * Wr[DD + 32 + lane];
#pragma unroll
    for (int s = 16; s > 0; s >>= 1) acc += __shfl_down_sync(0xffffffffu, acc, s);
    if (lane == 0) out[n] = acc + br[0];
}

// ---------------- launch --------------------------------------------------------
extern "C" void kernel_launch(void* const* d_in, const int* in_sizes, int n_in,
                              void* d_out, int out_size) {
    const float* x      = (const float*)d_in[0];
    const void*  eidx   = d_in[1];
    const float* ea     = (const float*)d_in[2];
    const void*  batch  = d_in[3];
    const float* degree = (const float*)d_in[4];
    int wb = (n_in >= 20) ? 6 : 5;
    const float* W_en  = (const float*)d_in[wb + 0];
    const float* b_en  = (const float*)d_in[wb + 1];
    const float* W_ene = (const float*)d_in[wb + 2];
    const float* b_ene = (const float*)d_in[wb + 3];
    const float* W_agg = (const float*)d_in[wb + 4];
    const float* b_agg = (const float*)d_in[wb + 5];
    const float* Wm    = (const float*)d_in[wb + 6];
    const float* bm    = (const float*)d_in[wb + 7];
    const float* Wu    = (const float*)d_in[wb + 8];
    const float* bu    = (const float*)d_in[wb + 9];
    const float* W_g   = (const float*)d_in[wb + 10];
    const float* b_g   = (const float*)d_in[wb + 11];
    const float* W_r   = (const float*)d_in[wb + 12];
    const float* b_r   = (const float*)d_in[wb + 13];
    float* out = (float*)d_out;

    const int LAYER_SMEM = 2 * 2 * DD * PAD2 * (int)sizeof(float);  // 69632
    cudaFuncSetAttribute(k_layer, cudaFuncAttributeMaxDynamicSharedMemorySize,
                         LAYER_SMEM);

    k_init<<<(NN / 4 + 255) / 256, 256>>>((const int*)eidx, (const int*)batch);
    k_conv_edges<<<(NE + 255) / 256, 256>>>(eidx);
    k_conv_batch<<<(NN + 255) / 256, 256>>>(batch, degree);

    // CSR build
    k_scanA<<<NB_SCAN, 256>>>();
    k_scanB<<<1, 256>>>();
    k_scanC<<<NB_SCAN, 256>>>();
    k_scatter<<<(NE + 255) / 256, 256>>>(eidx, ea);

    k_nodeemb<<<(NN + 3) / 4, 256>>>(x, W_en, b_en);
    k_node2<<<(NN + NT2 - 1) / NT2, 256>>>(x, W_ene, b_ene, W_agg, b_agg);

    for (int l = 0; l < 3; l++) {
        k_layer<<<(NN + NT - 1) / NT, 256, LAYER_SMEM>>>(
            Wm + l * 2 * DD * DD, bm + l * DD,
            Wu + l * 2 * DD * DD, bu + l * DD, l & 1);
    }

    k_gscatter<<<(NN + 255) / 256, 256>>>();
    k_ggemm<<<(GG * DD + 255) / 256, 256>>>(W_g, b_g);
    k_final<<<(NN * 32 + 255) / 256, 256>>>(W_r, b_r, out);
}

// round 13
// speedup vs baseline: 1.0263x; 1.0263x over previous
#include <cuda_runtime.h>

#define NN 50000
#define NE 800000
#define DIN 7
#define DD 64
#define GG 64
#define NB_SCAN 196   // ceil(NN/256)
#define NT 32         // nodes per k_layer / k_node2 block
#define PAD 36        // padded row stride (144B: 16B aligned)

// ---------------- scratch (device globals; no allocation allowed) -------------
__device__ float g_xembA[NN * DD];
__device__ float g_xembB[NN * DD];
__device__ float g_xaggemb[NN * DD];
__device__ float g_degmax[GG];
__device__ float g_gagg[GG * DD];
__device__ float g_gcnt[GG];
__device__ float g_gout[GG * DD];
__device__ int2  g_cw[NE];          // sorted-by-row packed {col, w_bits}
__device__ int   g_rowptr[NN + 1];
__device__ int   g_cnt[NN];         // histogram
__device__ int   g_cnt2[NN];        // scatter cursors
__device__ int   g_bsum[NB_SCAN];
__device__ int   g_boff[NB_SCAN];
__device__ int   g_batch[NN];
__device__ int   g_flag[2];         // 1 => input is int64, 0 => int32

// ---------------- packed f32x2 helpers (sm_100+) -------------------------------
__device__ __forceinline__ unsigned long long pack2(float w) {
    unsigned long long r;
    asm("mov.b64 %0, {%1, %1};" : "=l"(r) : "f"(w));
    return r;
}
__device__ __forceinline__ void ffma2(unsigned long long& d,
                                      unsigned long long a, unsigned long long b) {
    asm("fma.rn.f32x2 %0, %1, %2, %0;" : "+l"(d) : "l"(a), "l"(b));
}
__device__ __forceinline__ void lds_pair(unsigned long long& a, unsigned long long& b,
                                         const float* p) {
    unsigned addr = (unsigned)__cvta_generic_to_shared(p);
    asm("ld.shared.v2.b64 {%0, %1}, [%2];" : "=l"(a), "=l"(b) : "r"(addr));
}
__device__ __forceinline__ float2 unpack2(unsigned long long v) {
    float2 f;
    asm("mov.b64 {%0, %1}, %2;" : "=f"(f.x), "=f"(f.y) : "l"(v));
    return f;
}

// ---------------- vector reduction helper (sm_90+) ----------------------------
__device__ __forceinline__ void red4(float* p, float4 v) {
    asm volatile("red.global.add.v4.f32 [%0], {%1,%2,%3,%4};"
                 :: "l"(p), "f"(v.x), "f"(v.y), "f"(v.z), "f"(v.w)
                 : "memory");
}

// ---------------- fused zero + dtype detection --------------------------------
// All blocks zero scratch; block 0's first two warps detect int64 vs int32 by
// sampling odd 32-bit words (int64 high halves are all zero for graph indices).
__global__ void k_init(const int* __restrict__ eidx, const int* __restrict__ batch) {
    int i = blockIdx.x * blockDim.x + threadIdx.x;
    int4 zi = make_int4(0, 0, 0, 0);
    float4 zf = make_float4(0.f, 0.f, 0.f, 0.f);
    if (i < NN / 4) { ((int4*)g_cnt)[i] = zi; ((int4*)g_cnt2)[i] = zi; }
    if (i < GG * 16) ((float4*)g_gagg)[i] = zf;
    if (i < GG / 4) { ((float4*)g_degmax)[i] = zf; ((float4*)g_gcnt)[i] = zf; }
    if (blockIdx.x == 0 && threadIdx.x < 64) {
        int slot = threadIdx.x >> 5;
        const int* p = slot ? batch : eidx;
        int n32 = slot ? NN : 2 * NE;
        int t = threadIdx.x & 31;
        long long half = (long long)(n32 - 1) / 2;
        long long k = (half > 32) ? ((long long)t * (half - 1)) / 31 : (long long)t;
        long long idx = 2 * k + 1;
        int v = (idx < n32) ? p[idx] : 0;
        unsigned m = __ballot_sync(0xffffffffu, v == 0);
        if (t == 0) g_flag[slot] = (m == 0xffffffffu) ? 1 : 0;
    }
}

// ---------------- row histogram (reads only the row half) ----------------------
__global__ void k_conv_edges(const void* __restrict__ p) {
    int e = blockIdx.x * blockDim.x + threadIdx.x;
    if (e >= NE) return;
    int r;
    if (g_flag[0]) r = (int)((const long long*)p)[NE + e];
    else           r = ((const int*)p)[NE + e];
    atomicAdd(&g_cnt[r], 1);
}

// batch conversion + per-graph degree max + per-graph node count (fused)
__global__ void k_conv_batch(const void* __restrict__ p, const float* __restrict__ degree) {
    int n = blockIdx.x * blockDim.x + threadIdx.x;
    if (n >= NN) return;
    int b;
    if (g_flag[1]) b = (int)((const long long*)p)[n];
    else           b = ((const int*)p)[n];
    g_batch[n] = b;
    atomicMax((unsigned int*)&g_degmax[b], __float_as_uint(degree[n]));
    atomicAdd(&g_gcnt[b], 1.f);
}

// ---------------- 3-kernel exclusive scan of g_cnt -> g_rowptr -----------------
__global__ void k_scanA() {                         // 196 blocks x 256
    __shared__ int sh[256];
    int i = blockIdx.x * 256 + threadIdx.x;
    sh[threadIdx.x] = (i < NN) ? g_cnt[i] : 0;
    __syncthreads();
    for (int s = 128; s > 0; s >>= 1) {
        if (threadIdx.x < s) sh[threadIdx.x] += sh[threadIdx.x + s];
        __syncthreads();
    }
    if (threadIdx.x == 0) g_bsum[blockIdx.x] = sh[0];
}

__global__ void k_scanB() {                         // 1 block x 256
    __shared__ int sh[256];
    int t = threadIdx.x;
    int v = (t < NB_SCAN) ? g_bsum[t] : 0;
    sh[t] = v;
    __syncthreads();
    for (int s = 1; s < 256; s <<= 1) {
        int add = (t >= s) ? sh[t - s] : 0;
        __syncthreads();
        sh[t] += add;
        __syncthreads();
    }
    if (t < NB_SCAN) g_boff[t] = sh[t] - v;         // exclusive
    if (t == 0) g_rowptr[NN] = NE;
}

__global__ void k_scanC() {                         // 196 blocks x 256
    __shared__ int sh[256];
    int t = threadIdx.x;
    int i = blockIdx.x * 256 + t;
    int v = (i < NN) ? g_cnt[i] : 0;
    sh[t] = v;
    __syncthreads();
    for (int s = 1; s < 256; s <<= 1) {
        int add = (t >= s) ? sh[t - s] : 0;
        __syncthreads();
        sh[t] += add;
        __syncthreads();
    }
    if (i < NN) g_rowptr[i] = g_boff[blockIdx.x] + sh[t] - v;
}

// scatter edges into CSR order, packing {col, w}; reads raw edge input again
__global__ void k_scatter(const void* __restrict__ p, const float* __restrict__ ea) {
    int e = blockIdx.x * blockDim.x + threadIdx.x;
    if (e >= NE) return;
    int c, r;
    if (g_flag[0]) {
        const long long* q = (const long long*)p;
        c = (int)q[e]; r = (int)q[NE + e];
    } else {
        const int* q = (const int*)p;
        c = q[e]; r = q[NE + e];
    }
    int pos = g_rowptr[r] + atomicAdd(&g_cnt2[r], 1);
    g_cw[pos] = make_int2(c, __float_as_int(ea[e]));
}

// ---------------- node embedding: x_emb = relu(x @ W_en + b_en) ---------------
__global__ void k_nodeemb(const float* __restrict__ x,
                          const float* __restrict__ W,
                          const float* __restrict__ b) {
    __shared__ float sx[4][DIN];
    int gl = threadIdx.x >> 6, o = threadIdx.x & 63;
    int n = blockIdx.x * 4 + gl;
    if (o < DIN && n < NN) sx[gl][o] = x[n * DIN + o];
    __syncthreads();
    if (n >= NN) return;
    float acc = b[o];
#pragma unroll
    for (int i = 0; i < DIN; i++) acc = fmaf(sx[gl][i], W[i * DD + o], acc);
    g_xembA[n * DD + o] = fmaxf(acc, 0.f);
}

// ---------------- fused stage-2: 32 nodes/block -------------------------------
__global__ void __launch_bounds__(256) k_node2(
        const float* __restrict__ x,
        const float* __restrict__ Wene, const float* __restrict__ bene,
        const float* __restrict__ Wagg, const float* __restrict__ bagg) {
    __shared__ __align__(16) float act[DD][PAD];
    __shared__ float ne[NT][9];
    __shared__ float rcs[NT];
    int t = threadIdx.x;
    int n0 = blockIdx.x * NT;

    // ---- gather (unroll 4 for MLP) ----
    {
        int ln = t >> 3, f = t & 7;
        int n = n0 + ln;
        float acc = 0.f;
        int deg = 0;
        if (n < NN) {
            int p0 = g_rowptr[n];
            deg = g_rowptr[n + 1] - p0;
            int k = 0;
            for (; k + 4 <= deg; k += 4) {
                int2 c0 = g_cw[p0 + k],     c1 = g_cw[p0 + k + 1];
                int2 c2 = g_cw[p0 + k + 2], c3 = g_cw[p0 + k + 3];
                float v0 = (f < 7) ? x[c0.x * DIN + f] : __int_as_float(c0.y);
                float v1 = (f < 7) ? x[c1.x * DIN + f] : __int_as_float(c1.y);
                float v2 = (f < 7) ? x[c2.x * DIN + f] : __int_as_float(c2.y);
                float v3 = (f < 7) ? x[c3.x * DIN + f] : __int_as_float(c3.y);
                acc += (v0 + v1) + (v2 + v3);
            }
            for (; k < deg; k++) {
                int2 cw = g_cw[p0 + k];
                acc += (f < 7) ? x[cw.x * DIN + f] : __int_as_float(cw.y);
            }
        }
        ne[ln][f] = acc;
        if (f == 0) rcs[ln] = 1.f / fmaxf((float)deg, 1.f);
    }
    __syncthreads();

    // ---- ene GEMM + degree slot -> act[o][node] ----
    {
        int gl = t >> 6, o = t & 63;
        float wv[8], b0 = 0.f;
        if (o < 63) {
            b0 = bene[o];
#pragma unroll
            for (int j = 0; j < 8; j++) wv[j] = Wene[j * 63 + o];
        }
#pragma unroll
        for (int i = 0; i < 8; i++) {
            int node = gl * 8 + i;
            int n = n0 + node;
            float v;
            if (o < 63) {
                float rc = rcs[node];
                float a = b0;
#pragma unroll
                for (int j = 0; j < 8; j++) a = fmaf(ne[node][j] * rc, wv[j], a);
                v = fmaxf(a, 0.f);
            } else {
                v = (n < NN) ? g_degmax[g_batch[n]] : 0.f;
            }
            act[o][node] = v;
        }
    }
    __syncthreads();

    // ---- Wagg GEMM (FFMA2): x_agg_emb = relu(act @ Wagg + bagg) ----
    {
        int gl = t >> 6, o = t & 63;
        unsigned long long m01, m23, m45, m67;
        m01 = m23 = m45 = m67 = pack2(bagg[o]);
#pragma unroll 4
        for (int j = 0; j < DD; j++) {
            unsigned long long ww = pack2(Wagg[j * DD + o]);
            unsigned long long a0, a1, a2, a3;
            lds_pair(a0, a1, &act[j][gl * 8]);
            lds_pair(a2, a3, &act[j][gl * 8 + 4]);
            ffma2(m01, ww, a0); ffma2(m23, ww, a1);
            ffma2(m45, ww, a2); ffma2(m67, ww, a3);
        }
        float2 r0 = unpack2(m01), r1 = unpack2(m23);
        float2 r2 = unpack2(m45), r3 = unpack2(m67);
        float res[8] = {r0.x, r0.y, r1.x, r1.y, r2.x, r2.y, r3.x, r3.y};
#pragma unroll
        for (int i = 0; i < 8; i++) {
            int n = n0 + gl * 8 + i;
            if (n < NN) g_xaggemb[n * DD + o] = fmaxf(res[i], 0.f);
        }
    }
}

// ---------------- fused per-layer: float2 gather + FFMA2 GEMMs (NT=32) --------
// Gather: warp-per-node (lane o2 = feature pair), 4 reps x 8 nodes.
// GEMM: thread (o, gl) computes column o for 8 nodes via 4 f32x2 accumulators.
__global__ void __launch_bounds__(256) k_layer(
        const float* __restrict__ Wm, const float* __restrict__ bm,
        const float* __restrict__ Wu, const float* __restrict__ bu,
        int flip) {
    const float* __restrict__ src = flip ? g_xembB : g_xembA;
    float*       __restrict__ dst = flip ? g_xembA : g_xembB;
    __shared__ __align__(16) float act1[2 * DD][PAD];   // [xagg*rc ; xaggemb]
    __shared__ __align__(16) float act2[2 * DD][PAD];   // [x_emb ; m]
    int t = threadIdx.x;
    int n0 = blockIdx.x * NT;

    // ---- gather phase ----
    {
        int o2 = t & 31;          // feature pair: features 2*o2, 2*o2+1
        int w8 = t >> 5;          // node slot 0..7
#pragma unroll 1
        for (int rep = 0; rep < 4; rep++) {
            int ln = rep * 8 + w8;
            int n = n0 + ln;
            unsigned long long acc = 0ULL, xe = 0ULL, xae = 0ULL;
            int deg = 0;
            if (n < NN) {
                int p0 = g_rowptr[n];
                deg = g_rowptr[n + 1] - p0;
                int k = 0;
                for (; k + 4 <= deg; k += 4) {
                    int2 c0 = g_cw[p0 + k],     c1 = g_cw[p0 + k + 1];
                    int2 c2 = g_cw[p0 + k + 2], c3 = g_cw[p0 + k + 3];
                    unsigned long long v0 = *(const unsigned long long*)&src[c0.x * DD + 2 * o2];
                    unsigned long long v1 = *(const unsigned long long*)&src[c1.x * DD + 2 * o2];
                    unsigned long long v2 = *(const unsigned long long*)&src[c2.x * DD + 2 * o2];
                    unsigned long long v3 = *(const unsigned long long*)&src[c3.x * DD + 2 * o2];
                    ffma2(acc, pack2(__int_as_float(c0.y)), v0);
                    ffma2(acc, pack2(__int_as_float(c1.y)), v1);
                    ffma2(acc, pack2(__int_as_float(c2.y)), v2);
                    ffma2(acc, pack2(__int_as_float(c3.y)), v3);
                }
                for (; k < deg; k++) {
                    int2 cw = g_cw[p0 + k];
                    unsigned long long v = *(const unsigned long long*)&src[cw.x * DD + 2 * o2];
                    ffma2(acc, pack2(__int_as_float(cw.y)), v);
                }
                xe  = *(const unsigned long long*)&src[n * DD + 2 * o2];
                xae = *(const unsigned long long*)&g_xaggemb[n * DD + 2 * o2];
            }
            float rc = 1.f / fmaxf((float)deg, 1.f);
            float2 a = unpack2(acc), x2 = unpack2(xe), xa2 = unpack2(xae);
            act1[2 * o2][ln]          = a.x * rc;
            act1[2 * o2 + 1][ln]      = a.y * rc;
            act1[DD + 2 * o2][ln]     = xa2.x;
            act1[DD + 2 * o2 + 1][ln] = xa2.y;
            act2[2 * o2][ln]          = x2.x;
            act2[2 * o2 + 1][ln]      = x2.y;
        }
    }
    __syncthreads();

    int gl = t >> 6, o = t & 63;

    // ---- GEMM1: m = relu([xagg, xaggemb] @ Wm + bm) ----
    {
        unsigned long long m01, m23, m45, m67;
        m01 = m23 = m45 = m67 = pack2(bm[o]);
#pragma unroll 4
        for (int j = 0; j < 2 * DD; j++) {
            unsigned long long ww = pack2(Wm[j * DD + o]);
            unsigned long long a0, a1, a2, a3;
            lds_pair(a0, a1, &act1[j][gl * 8]);
            lds_pair(a2, a3, &act1[j][gl * 8 + 4]);
            ffma2(m01, ww, a0); ffma2(m23, ww, a1);
            ffma2(m45, ww, a2); ffma2(m67, ww, a3);
        }
        float2 r0 = unpack2(m01), r1 = unpack2(m23);
        float2 r2 = unpack2(m45), r3 = unpack2(m67);
        float* row = &act2[DD + o][gl * 8];
        row[0] = fmaxf(r0.x, 0.f); row[1] = fmaxf(r0.y, 0.f);
        row[2] = fmaxf(r1.x, 0.f); row[3] = fmaxf(r1.y, 0.f);
        row[4] = fmaxf(r2.x, 0.f); row[5] = fmaxf(r2.y, 0.f);
        row[6] = fmaxf(r3.x, 0.f); row[7] = fmaxf(r3.y, 0.f);
    }
    __syncthreads();

    // ---- GEMM2: x_emb' = relu([x_emb, m] @ Wu + bu) ----
    {
        unsigned long long m01, m23, m45, m67;
        m01 = m23 = m45 = m67 = pack2(bu[o]);
#pragma unroll 4
        for (int j = 0; j < 2 * DD; j++) {
            unsigned long long ww = pack2(Wu[j * DD + o]);
            unsigned long long a0, a1, a2, a3;
            lds_pair(a0, a1, &act2[j][gl * 8]);
            lds_pair(a2, a3, &act2[j][gl * 8 + 4]);
            ffma2(m01, ww, a0); ffma2(m23, ww, a1);
            ffma2(m45, ww, a2); ffma2(m67, ww, a3);
        }
        float2 r0 = unpack2(m01), r1 = unpack2(m23);
        float2 r2 = unpack2(m45), r3 = unpack2(m67);
        float res[8] = {r0.x, r0.y, r1.x, r1.y, r2.x, r2.y, r3.x, r3.y};
#pragma unroll
        for (int i = 0; i < 8; i++) {
            int n = n0 + gl * 8 + i;
            if (n < NN) dst[n * DD + o] = fmaxf(res[i], 0.f);
        }
    }
}

// ---------------- graph pooling: sorted-batch local accumulation --------------
__global__ void k_gscatter() {
    int idx = blockIdx.x * blockDim.x + threadIdx.x;   // 50000 threads
    int c  = idx & 15;
    int n0 = (idx >> 4) * 16;
    if (n0 >= NN) return;
    float4 acc = make_float4(0.f, 0.f, 0.f, 0.f);
    int curb = g_batch[n0];
#pragma unroll
    for (int k = 0; k < 16; k++) {
        int n = n0 + k;
        int b = g_batch[n];
        if (b != curb) {
            red4(g_gagg + curb * DD + c * 4, acc);
            acc = make_float4(0.f, 0.f, 0.f, 0.f);
            curb = b;
        }
        float4 v = ((const float4*)g_xembB)[n * 16 + c];
        acc.x += v.x; acc.y += v.y; acc.z += v.z; acc.w += v.w;
    }
    red4(g_gagg + curb * DD + c * 4, acc);
}

__global__ void k_ggemm(const float* __restrict__ Wg, const float* __restrict__ bg) {
    int idx = blockIdx.x * blockDim.x + threadIdx.x;
    if (idx >= GG * DD) return;
    int g = idx >> 6, o = idx & 63;
    float rc = 1.f / fmaxf(g_gcnt[g], 1.f);
    float acc = bg[o];
#pragma unroll 16
    for (int k = 0; k < DD; k++)
        acc = fmaf(g_gagg[g * DD + k] * rc, Wg[k * DD + o], acc);
    g_gout[idx] = acc;   // no relu (reference applies relu to the concat input)
}

// ---------------- readout: q = relu([gout[batch], x_emb]) @ W_r + b_r ----------
__global__ void k_final(const float* __restrict__ Wr, const float* __restrict__ br,
                        float* __restrict__ out) {
    int gidx = blockIdx.x * blockDim.x + threadIdx.x;
    int n = gidx >> 5;
    int lane = threadIdx.x & 31;
    if (n >= NN) return;
    int b = g_batch[n];
    float acc = fmaxf(g_gout[b * DD + lane], 0.f)       * Wr[lane]
              + fmaxf(g_gout[b * DD + 32 + lane], 0.f)  * Wr[32 + lane]
              + g_xembB[n * DD + lane]                   * Wr[DD + lane]      // x_emb >= 0
              + g_xembB[n * DD + 32 + lane]              * Wr[DD + 32 + lane];
#pragma unroll
    for (int s = 16; s > 0; s >>= 1) acc += __shfl_down_sync(0xffffffffu, acc, s);
    if (lane == 0) out[n] = acc + br[0];
}

// ---------------- launch --------------------------------------------------------
extern "C" void kernel_launch(void* const* d_in, const int* in_sizes, int n_in,
                              void* d_out, int out_size) {
    const float* x      = (const float*)d_in[0];
    const void*  eidx   = d_in[1];
    const float* ea     = (const float*)d_in[2];
    const void*  batch  = d_in[3];
    const float* degree = (const float*)d_in[4];
    int wb = (n_in >= 20) ? 6 : 5;
    const float* W_en  = (const float*)d_in[wb + 0];
    const float* b_en  = (const float*)d_in[wb + 1];
    const float* W_ene = (const float*)d_in[wb + 2];
    const float* b_ene = (const float*)d_in[wb + 3];
    const float* W_agg = (const float*)d_in[wb + 4];
    const float* b_agg = (const float*)d_in[wb + 5];
    const float* Wm    = (const float*)d_in[wb + 6];
    const float* bm    = (const float*)d_in[wb + 7];
    const float* Wu    = (const float*)d_in[wb + 8];
    const float* bu    = (const float*)d_in[wb + 9];
    const float* W_g   = (const float*)d_in[wb + 10];
    const float* b_g   = (const float*)d_in[wb + 11];
    const float* W_r   = (const float*)d_in[wb + 12];
    const float* b_r   = (const float*)d_in[wb + 13];
    float* out = (float*)d_out;

    k_init<<<(NN / 4 + 255) / 256, 256>>>((const int*)eidx, (const int*)batch);
    k_conv_edges<<<(NE + 255) / 256, 256>>>(eidx);
    k_conv_batch<<<(NN + 255) / 256, 256>>>(batch, degree);
    k_nodeemb<<<(NN + 3) / 4, 256>>>(x, W_en, b_en);

    // CSR build
    k_scanA<<<NB_SCAN, 256>>>();
    k_scanB<<<1, 256>>>();
    k_scanC<<<NB_SCAN, 256>>>();
    k_scatter<<<(NE + 255) / 256, 256>>>(eidx, ea);

    k_node2<<<(NN + NT - 1) / NT, 256>>>(x, W_ene, b_ene, W_agg, b_agg);

    for (int l = 0; l < 3; l++) {
        k_layer<<<(NN + NT - 1) / NT, 256>>>(Wm + l * 2 * DD * DD, bm + l * DD,
                                             Wu + l * 2 * DD * DD, bu + l * DD, l & 1);
    }

    k_gscatter<<<(NN + 255) / 256, 256>>>();
    k_ggemm<<<(GG * DD + 255) / 256, 256>>>(W_g, b_g);
    k_final<<<(NN * 32 + 255) / 256, 256>>>(W_r, b_r, out);
}

// round 15
// speedup vs baseline: 1.0267x; 1.0004x over previous
#include <cuda_runtime.h>

#define NN 50000
#define NE 800000
#define DIN 7
#define DD 64
#define GG 64
#define NB_SCAN 196   // ceil(NN/256)
#define NT 32         // nodes per GEMM-kernel block
#define PAD 36        // padded row stride (144B: 16B aligned)

// ---------------- scratch (device globals; no allocation allowed) -------------
__device__ float g_xembA[NN * DD];
__device__ float g_xembB[NN * DD];
__device__ float g_xaggemb[NN * DD];
__device__ float g_xagg[NN * DD];   // gather output (rc-scaled)
__device__ float g_degmax[GG];
__device__ float g_gagg[GG * DD];
__device__ float g_gcnt[GG];
__device__ float g_gout[GG * DD];
__device__ int2  g_cw[NE];          // sorted-by-row packed {col, w_bits}
__device__ int   g_rowptr[NN + 1];
__device__ int   g_cnt[NN];         // histogram
__device__ int   g_cnt2[NN];        // scatter cursors
__device__ int   g_bsum[NB_SCAN];
__device__ int   g_boff[NB_SCAN];
__device__ int   g_batch[NN];
__device__ int   g_flag[2];         // 1 => input is int64, 0 => int32

// ---------------- packed f32x2 helpers (sm_100+) -------------------------------
__device__ __forceinline__ unsigned long long pack2(float w) {
    unsigned long long r;
    asm("mov.b64 %0, {%1, %1};" : "=l"(r) : "f"(w));
    return r;
}
__device__ __forceinline__ void ffma2(unsigned long long& d,
                                      unsigned long long a, unsigned long long b) {
    asm("fma.rn.f32x2 %0, %1, %2, %0;" : "+l"(d) : "l"(a), "l"(b));
}
__device__ __forceinline__ void lds_pair(unsigned long long& a, unsigned long long& b,
                                         const float* p) {
    unsigned addr = (unsigned)__cvta_generic_to_shared(p);
    asm("ld.shared.v2.b64 {%0, %1}, [%2];" : "=l"(a), "=l"(b) : "r"(addr));
}
__device__ __forceinline__ float2 unpack2(unsigned long long v) {
    float2 f;
    asm("mov.b64 {%0, %1}, %2;" : "=f"(f.x), "=f"(f.y) : "l"(v));
    return f;
}

// ---------------- vector reduction helper (sm_90+) ----------------------------
__device__ __forceinline__ void red4(float* p, float4 v) {
    asm volatile("red.global.add.v4.f32 [%0], {%1,%2,%3,%4};"
                 :: "l"(p), "f"(v.x), "f"(v.y), "f"(v.z), "f"(v.w)
                 : "memory");
}

// ---------------- fused zero + dtype detection --------------------------------
__global__ void k_init(const int* __restrict__ eidx, const int* __restrict__ batch) {
    int i = blockIdx.x * blockDim.x + threadIdx.x;
    int4 zi = make_int4(0, 0, 0, 0);
    float4 zf = make_float4(0.f, 0.f, 0.f, 0.f);
    if (i < NN / 4) { ((int4*)g_cnt)[i] = zi; ((int4*)g_cnt2)[i] = zi; }
    if (i < GG * 16) ((float4*)g_gagg)[i] = zf;
    if (i < GG / 4) { ((float4*)g_degmax)[i] = zf; ((float4*)g_gcnt)[i] = zf; }
    if (blockIdx.x == 0 && threadIdx.x < 64) {
        int slot = threadIdx.x >> 5;
        const int* p = slot ? batch : eidx;
        int n32 = slot ? NN : 2 * NE;
        int t = threadIdx.x & 31;
        long long half = (long long)(n32 - 1) / 2;
        long long k = (half > 32) ? ((long long)t * (half - 1)) / 31 : (long long)t;
        long long idx = 2 * k + 1;
        int v = (idx < n32) ? p[idx] : 0;
        unsigned m = __ballot_sync(0xffffffffu, v == 0);
        if (t == 0) g_flag[slot] = (m == 0xffffffffu) ? 1 : 0;
    }
}

// ---------------- row histogram (reads only the row half) ----------------------
__global__ void k_conv_edges(const void* __restrict__ p) {
    int e = blockIdx.x * blockDim.x + threadIdx.x;
    if (e >= NE) return;
    int r;
    if (g_flag[0]) r = (int)((const long long*)p)[NE + e];
    else           r = ((const int*)p)[NE + e];
    atomicAdd(&g_cnt[r], 1);
}

// batch conversion + per-graph degree max + per-graph node count (fused)
__global__ void k_conv_batch(const void* __restrict__ p, const float* __restrict__ degree) {
    int n = blockIdx.x * blockDim.x + threadIdx.x;
    if (n >= NN) return;
    int b;
    if (g_flag[1]) b = (int)((const long long*)p)[n];
    else           b = ((const int*)p)[n];
    g_batch[n] = b;
    atomicMax((unsigned int*)&g_degmax[b], __float_as_uint(degree[n]));
    atomicAdd(&g_gcnt[b], 1.f);
}

// ---------------- 3-kernel exclusive scan of g_cnt -> g_rowptr -----------------
__global__ void k_scanA() {                         // 196 blocks x 256
    __shared__ int sh[256];
    int i = blockIdx.x * 256 + threadIdx.x;
    sh[threadIdx.x] = (i < NN) ? g_cnt[i] : 0;
    __syncthreads();
    for (int s = 128; s > 0; s >>= 1) {
        if (threadIdx.x < s) sh[threadIdx.x] += sh[threadIdx.x + s];
        __syncthreads();
    }
    if (threadIdx.x == 0) g_bsum[blockIdx.x] = sh[0];
}

__global__ void k_scanB() {                         // 1 block x 256
    __shared__ int sh[256];
    int t = threadIdx.x;
    int v = (t < NB_SCAN) ? g_bsum[t] : 0;
    sh[t] = v;
    __syncthreads();
    for (int s = 1; s < 256; s <<= 1) {
        int add = (t >= s) ? sh[t - s] : 0;
        __syncthreads();
        sh[t] += add;
        __syncthreads();
    }
    if (t < NB_SCAN) g_boff[t] = sh[t] - v;         // exclusive
    if (t == 0) g_rowptr[NN] = NE;
}

__global__ void k_scanC() {                         // 196 blocks x 256
    __shared__ int sh[256];
    int t = threadIdx.x;
    int i = blockIdx.x * 256 + t;
    int v = (i < NN) ? g_cnt[i] : 0;
    sh[t] = v;
    __syncthreads();
    for (int s = 1; s < 256; s <<= 1) {
        int add = (t >= s) ? sh[t - s] : 0;
        __syncthreads();
        sh[t] += add;
        __syncthreads();
    }
    if (i < NN) g_rowptr[i] = g_boff[blockIdx.x] + sh[t] - v;
}

// scatter edges into CSR order, packing {col, w}; reads raw edge input again
__global__ void k_scatter(const void* __restrict__ p, const float* __restrict__ ea) {
    int e = blockIdx.x * blockDim.x + threadIdx.x;
    if (e >= NE) return;
    int c, r;
    if (g_flag[0]) {
        const long long* q = (const long long*)p;
        c = (int)q[e]; r = (int)q[NE + e];
    } else {
        const int* q = (const int*)p;
        c = q[e]; r = q[NE + e];
    }
    int pos = g_rowptr[r] + atomicAdd(&g_cnt2[r], 1);
    g_cw[pos] = make_int2(c, __float_as_int(ea[e]));
}

// ---------------- node embedding: x_emb = relu(x @ W_en + b_en), 32 nodes/blk --
__global__ void __launch_bounds__(256) k_nodeemb(
        const float* __restrict__ x, const float* __restrict__ W,
        const float* __restrict__ b) {
    __shared__ float sx[NT][8];
    int t = threadIdx.x;
    int n0 = blockIdx.x * NT;
    if (t < NT * DIN) {
        int ln = t / DIN, f = t - ln * DIN;
        int n = n0 + ln;
        sx[ln][f] = (n < NN) ? x[n * DIN + f] : 0.f;
    }
    __syncthreads();
    int gl = t >> 6, o = t & 63;
    float wv[DIN];
#pragma unroll
    for (int i = 0; i < DIN; i++) wv[i] = W[i * DD + o];
    float b0 = b[o];
#pragma unroll
    for (int i = 0; i < 8; i++) {
        int node = gl * 8 + i;
        int n = n0 + node;
        float acc = b0;
#pragma unroll
        for (int j = 0; j < DIN; j++) acc = fmaf(sx[node][j], wv[j], acc);
        if (n < NN) g_xembA[n * DD + o] = fmaxf(acc, 0.f);
    }
}

// ---------------- fused stage-2: 32 nodes/block -------------------------------
__global__ void __launch_bounds__(256) k_node2(
        const float* __restrict__ x,
        const float* __restrict__ Wene, const float* __restrict__ bene,
        const float* __restrict__ Wagg, const float* __restrict__ bagg) {
    __shared__ __align__(16) float act[DD][PAD];
    __shared__ float ne[NT][9];
    __shared__ float rcs[NT];
    int t = threadIdx.x;
    int n0 = blockIdx.x * NT;

    // ---- gather (unroll 4 for MLP) ----
    {
        int ln = t >> 3, f = t & 7;
        int n = n0 + ln;
        float acc = 0.f;
        int deg = 0;
        if (n < NN) {
            int p0 = g_rowptr[n];
            deg = g_rowptr[n + 1] - p0;
            int k = 0;
            for (; k + 4 <= deg; k += 4) {
                int2 c0 = g_cw[p0 + k],     c1 = g_cw[p0 + k + 1];
                int2 c2 = g_cw[p0 + k + 2], c3 = g_cw[p0 + k + 3];
                float v0 = (f < 7) ? x[c0.x * DIN + f] : __int_as_float(c0.y);
                float v1 = (f < 7) ? x[c1.x * DIN + f] : __int_as_float(c1.y);
                float v2 = (f < 7) ? x[c2.x * DIN + f] : __int_as_float(c2.y);
                float v3 = (f < 7) ? x[c3.x * DIN + f] : __int_as_float(c3.y);
                acc += (v0 + v1) + (v2 + v3);
            }
            for (; k < deg; k++) {
                int2 cw = g_cw[p0 + k];
                acc += (f < 7) ? x[cw.x * DIN + f] : __int_as_float(cw.y);
            }
        }
        ne[ln][f] = acc;
        if (f == 0) rcs[ln] = 1.f / fmaxf((float)deg, 1.f);
    }
    __syncthreads();

    // ---- ene GEMM + degree slot -> act[o][node] ----
    {
        int gl = t >> 6, o = t & 63;
        float wv[8], b0 = 0.f;
        if (o < 63) {
            b0 = bene[o];
#pragma unroll
            for (int j = 0; j < 8; j++) wv[j] = Wene[j * 63 + o];
        }
#pragma unroll
        for (int i = 0; i < 8; i++) {
            int node = gl * 8 + i;
            int n = n0 + node;
            float v;
            if (o < 63) {
                float rc = rcs[node];
                float a = b0;
#pragma unroll
                for (int j = 0; j < 8; j++) a = fmaf(ne[node][j] * rc, wv[j], a);
                v = fmaxf(a, 0.f);
            } else {
                v = (n < NN) ? g_degmax[g_batch[n]] : 0.f;
            }
            act[o][node] = v;
        }
    }
    __syncthreads();

    // ---- Wagg GEMM (FFMA2): x_agg_emb = relu(act @ Wagg + bagg) ----
    {
        int gl = t >> 6, o = t & 63;
        unsigned long long m01, m23, m45, m67;
        m01 = m23 = m45 = m67 = pack2(bagg[o]);
#pragma unroll 4
        for (int j = 0; j < DD; j++) {
            unsigned long long ww = pack2(Wagg[j * DD + o]);
            unsigned long long a0, a1, a2, a3;
            lds_pair(a0, a1, &act[j][gl * 8]);
            lds_pair(a2, a3, &act[j][gl * 8 + 4]);
            ffma2(m01, ww, a0); ffma2(m23, ww, a1);
            ffma2(m45, ww, a2); ffma2(m67, ww, a3);
        }
        float2 r0 = unpack2(m01), r1 = unpack2(m23);
        float2 r2 = unpack2(m45), r3 = unpack2(m67);
        float res[8] = {r0.x, r0.y, r1.x, r1.y, r2.x, r2.y, r3.x, r3.y};
#pragma unroll
        for (int i = 0; i < 8; i++) {
            int n = n0 + gl * 8 + i;
            if (n < NN) g_xaggemb[n * DD + o] = fmaxf(res[i], 0.f);
        }
    }
}

// ---------------- per-layer gather: warp-per-node, no block sync ---------------
// 50k independent warps; scheduler absorbs degree imbalance. Writes g_xagg
// (rc-scaled) as coalesced float2.
__global__ void __launch_bounds__(256) k_gather(int flip) {
    const float* __restrict__ src = flip ? g_xembB : g_xembA;
    int n  = (blockIdx.x * 256 + threadIdx.x) >> 5;
    int o2 = threadIdx.x & 31;
    if (n >= NN) return;
    int p0 = g_rowptr[n];
    int deg = g_rowptr[n + 1] - p0;
    unsigned long long acc = 0ULL;
    int k = 0;
    for (; k + 4 <= deg; k += 4) {
        int2 c0 = g_cw[p0 + k],     c1 = g_cw[p0 + k + 1];
        int2 c2 = g_cw[p0 + k + 2], c3 = g_cw[p0 + k + 3];
        unsigned long long v0 = *(const unsigned long long*)&src[c0.x * DD + 2 * o2];
        unsigned long long v1 = *(const unsigned long long*)&src[c1.x * DD + 2 * o2];
        unsigned long long v2 = *(const unsigned long long*)&src[c2.x * DD + 2 * o2];
        unsigned long long v3 = *(const unsigned long long*)&src[c3.x * DD + 2 * o2];
        ffma2(acc, pack2(__int_as_float(c0.y)), v0);
        ffma2(acc, pack2(__int_as_float(c1.y)), v1);
        ffma2(acc, pack2(__int_as_float(c2.y)), v2);
        ffma2(acc, pack2(__int_as_float(c3.y)), v3);
    }
    for (; k < deg; k++) {
        int2 cw = g_cw[p0 + k];
        unsigned long long v = *(const unsigned long long*)&src[cw.x * DD + 2 * o2];
        ffma2(acc, pack2(__int_as_float(cw.y)), v);
    }
    float rc = 1.f / fmaxf((float)deg, 1.f);
    float2 a = unpack2(acc);
    ((float2*)(g_xagg + n * DD))[o2] = make_float2(a.x * rc, a.y * rc);
}

// ---------------- per-layer node GEMMs (reads g_xagg) --------------------------
__global__ void __launch_bounds__(256) k_nodeupd(
        const float* __restrict__ Wm, const float* __restrict__ bm,
        const float* __restrict__ Wu, const float* __restrict__ bu,
        int flip) {
    const float* __restrict__ src = flip ? g_xembB : g_xembA;
    float*       __restrict__ dst = flip ? g_xembA : g_xembB;
    __shared__ __align__(16) float act1[2 * DD][PAD];   // [xagg ; xaggemb]
    __shared__ __align__(16) float act2[2 * DD][PAD];   // [x_emb ; m]
    int t = threadIdx.x;
    int n0 = blockIdx.x * NT;

    // ---- load phase: warp-per-node, coalesced float2, transposed store ----
    {
        int o2 = t & 31;
        int w8 = t >> 5;
#pragma unroll
        for (int rep = 0; rep < 4; rep++) {
            int ln = rep * 8 + w8;
            int n = n0 + ln;
            float2 xa = make_float2(0.f, 0.f), xae = xa, xe = xa;
            if (n < NN) {
                xa  = ((const float2*)(g_xagg    + n * DD))[o2];
                xae = ((const float2*)(g_xaggemb + n * DD))[o2];
                xe  = ((const float2*)(src       + n * DD))[o2];
            }
            act1[2 * o2][ln]          = xa.x;
            act1[2 * o2 + 1][ln]      = xa.y;
            act1[DD + 2 * o2][ln]     = xae.x;
            act1[DD + 2 * o2 + 1][ln] = xae.y;
            act2[2 * o2][ln]          = xe.x;
            act2[2 * o2 + 1][ln]      = xe.y;
        }
    }
    __syncthreads();

    int gl = t >> 6, o = t & 63;

    // ---- GEMM1: m = relu([xagg, xaggemb] @ Wm + bm) ----
    {
        unsigned long long m01, m23, m45, m67;
        m01 = m23 = m45 = m67 = pack2(bm[o]);
#pragma unroll 4
        for (int j = 0; j < 2 * DD; j++) {
            unsigned long long ww = pack2(Wm[j * DD + o]);
            unsigned long long a0, a1, a2, a3;
            lds_pair(a0, a1, &act1[j][gl * 8]);
            lds_pair(a2, a3, &act1[j][gl * 8 + 4]);
            ffma2(m01, ww, a0); ffma2(m23, ww, a1);
            ffma2(m45, ww, a2); ffma2(m67, ww, a3);
        }
        float2 r0 = unpack2(m01), r1 = unpack2(m23);
        float2 r2 = unpack2(m45), r3 = unpack2(m67);
        float* row = &act2[DD + o][gl * 8];
        row[0] = fmaxf(r0.x, 0.f); row[1] = fmaxf(r0.y, 0.f);
        row[2] = fmaxf(r1.x, 0.f); row[3] = fmaxf(r1.y, 0.f);
        row[4] = fmaxf(r2.x, 0.f); row[5] = fmaxf(r2.y, 0.f);
        row[6] = fmaxf(r3.x, 0.f); row[7] = fmaxf(r3.y, 0.f);
    }
    __syncthreads();

    // ---- GEMM2: x_emb' = relu([x_emb, m] @ Wu + bu) ----
    {
        unsigned long long m01, m23, m45, m67;
        m01 = m23 = m45 = m67 = pack2(bu[o]);
#pragma unroll 4
        for (int j = 0; j < 2 * DD; j++) {
            unsigned long long ww = pack2(Wu[j * DD + o]);
            unsigned long long a0, a1, a2, a3;
            lds_pair(a0, a1, &act2[j][gl * 8]);
            lds_pair(a2, a3, &act2[j][gl * 8 + 4]);
            ffma2(m01, ww, a0); ffma2(m23, ww, a1);
            ffma2(m45, ww, a2); ffma2(m67, ww, a3);
        }
        float2 r0 = unpack2(m01), r1 = unpack2(m23);
        float2 r2 = unpack2(m45), r3 = unpack2(m67);
        float res[8] = {r0.x, r0.y, r1.x, r1.y, r2.x, r2.y, r3.x, r3.y};
#pragma unroll
        for (int i = 0; i < 8; i++) {
            int n = n0 + gl * 8 + i;
            if (n < NN) dst[n * DD + o] = fmaxf(res[i], 0.f);
        }
    }
}

// ---------------- graph pooling: sorted-batch local accumulation --------------
__global__ void k_gscatter() {
    int idx = blockIdx.x * blockDim.x + threadIdx.x;   // 50000 threads
    int c  = idx & 15;
    int n0 = (idx >> 4) * 16;
    if (n0 >= NN) return;
    float4 acc = make_float4(0.f, 0.f, 0.f, 0.f);
    int curb = g_batch[n0];
#pragma unroll
    for (int k = 0; k < 16; k++) {
        int n = n0 + k;
        int b = g_batch[n];
        if (b != curb) {
            red4(g_gagg + curb * DD + c * 4, acc);
            acc = make_float4(0.f, 0.f, 0.f, 0.f);
            curb = b;
        }
        float4 v = ((const float4*)g_xembB)[n * 16 + c];
        acc.x += v.x; acc.y += v.y; acc.z += v.z; acc.w += v.w;
    }
    red4(g_gagg + curb * DD + c * 4, acc);
}

__global__ void k_ggemm(const float* __restrict__ Wg, const float* __restrict__ bg) {
    int idx = blockIdx.x * blockDim.x + threadIdx.x;
    if (idx >= GG * DD) return;
    int g = idx >> 6, o = idx & 63;
    float rc = 1.f / fmaxf(g_gcnt[g], 1.f);
    float acc = bg[o];
#pragma unroll 16
    for (int k = 0; k < DD; k++)
        acc = fmaf(g_gagg[g * DD + k] * rc, Wg[k * DD + o], acc);
    g_gout[idx] = acc;   // no relu (reference applies relu to the concat input)
}

// ---------------- readout: q = relu([gout[batch], x_emb]) @ W_r + b_r ----------
__global__ void k_final(const float* __restrict__ Wr, const float* __restrict__ br,
                        float* __restrict__ out) {
    int gidx = blockIdx.x * blockDim.x + threadIdx.x;
    int n = gidx >> 5;
    int lane = threadIdx.x & 31;
    if (n >= NN) return;
    int b = g_batch[n];
    float acc = fmaxf(g_gout[b * DD + lane], 0.f)       * Wr[lane]
              + fmaxf(g_gout[b * DD + 32 + lane], 0.f)  * Wr[32 + lane]
              + g_xembB[n * DD + lane]                   * Wr[DD + lane]      // x_emb >= 0
              + g_xembB[n * DD + 32 + lane]              * Wr[DD + 32 + lane];
#pragma unroll
    for (int s = 16; s > 0; s >>= 1) acc += __shfl_down_sync(0xffffffffu, acc, s);
    if (lane == 0) out[n] = acc + br[0];
}

// ---------------- launch --------------------------------------------------------
extern "C" void kernel_launch(void* const* d_in, const int* in_sizes, int n_in,
                              void* d_out, int out_size) {
    const float* x      = (const float*)d_in[0];
    const void*  eidx   = d_in[1];
    const float* ea     = (const float*)d_in[2];
    const void*  batch  = d_in[3];
    const float* degree = (const float*)d_in[4];
    int wb = (n_in >= 20) ? 6 : 5;
    const float* W_en  = (const float*)d_in[wb + 0];
    const float* b_en  = (const float*)d_in[wb + 1];
    const float* W_ene = (const float*)d_in[wb + 2];
    const float* b_ene = (const float*)d_in[wb + 3];
    const float* W_agg = (const float*)d_in[wb + 4];
    const float* b_agg = (const float*)d_in[wb + 5];
    const float* Wm    = (const float*)d_in[wb + 6];
    const float* bm    = (const float*)d_in[wb + 7];
    const float* Wu    = (const float*)d_in[wb + 8];
    const float* bu    = (const float*)d_in[wb + 9];
    const float* W_g   = (const float*)d_in[wb + 10];
    const float* b_g   = (const float*)d_in[wb + 11];
    const float* W_r   = (const float*)d_in[wb + 12];
    const float* b_r   = (const float*)d_in[wb + 13];
    float* out = (float*)d_out;

    k_init<<<(NN / 4 + 255) / 256, 256>>>((const int*)eidx, (const int*)batch);
    k_conv_edges<<<(NE + 255) / 256, 256>>>(eidx);
    k_conv_batch<<<(NN + 255) / 256, 256>>>(batch, degree);
    k_nodeemb<<<(NN + NT - 1) / NT, 256>>>(x, W_en, b_en);

    // CSR build
    k_scanA<<<NB_SCAN, 256>>>();
    k_scanB<<<1, 256>>>();
    k_scanC<<<NB_SCAN, 256>>>();
    k_scatter<<<(NE + 255) / 256, 256>>>(eidx, ea);

    k_node2<<<(NN + NT - 1) / NT, 256>>>(x, W_ene, b_ene, W_agg, b_agg);

    for (int l = 0; l < 3; l++) {
        k_gather<<<(NN * 32 + 255) / 256, 256>>>(l & 1);
        k_nodeupd<<<(NN + NT - 1) / NT, 256>>>(Wm + l * 2 * DD * DD, bm + l * DD,
                                               Wu + l * 2 * DD * DD, bu + l * DD, l & 1);
    }

    k_gscatter<<<(NN + 255) / 256, 256>>>();
    k_ggemm<<<(GG * DD + 255) / 256, 256>>>(W_g, b_g);
    k_final<<<(NN * 32 + 255) / 256, 256>>>(W_r, b_r, out);
}